// round 2
// baseline (speedup 1.0000x reference)
#include <cuda_runtime.h>
#include <cuda_bf16.h>

// Problem constants (from reference):
//   x:      [20000, 512]  float32
//   weight: [50]          float32
//   idx:    [50, 2000]    int32 (JAX downcasts int64 -> int32 without x64)
//   out:    [512 * 100000] float32, out[c*R + r] = x[idx[r], c] * w[r/2000]
#define N_FEATURE 20000
#define N_CELL    512
#define N_CT      50
#define M_PER_CT  2000
#define R_TOTAL   (N_CT * M_PER_CT)   // 100000

// 32x32 shared-memory transpose tile. Block = 32x8 threads, 4 rows each.
__global__ __launch_bounds__(256, 8)
void celltype_scale_transpose_kernel(const float* __restrict__ x,
                                     const float* __restrict__ w,
                                     const int* __restrict__ idx,
                                     float* __restrict__ out)
{
    __shared__ float tile[32][33];   // +1 pad: conflict-free transposed read

    const int r0 = blockIdx.x * 32;          // 3125 tiles along r
    const int c0 = blockIdx.y * 32;          // 16 tiles along c
    const int tx = threadIdx.x;              // 0..31
    const int ty = threadIdx.y;              // 0..7

    // Load phase: 32 gathered rows, 32 consecutive columns -> 128B coalesced.
    #pragma unroll
    for (int j = 0; j < 4; j++) {
        const int rr = ty + j * 8;           // row within tile
        const int r  = r0 + rr;              // global z-row
        const int srow = idx[r];             // uniform across warp -> broadcast
        const float wv = w[r / M_PER_CT];
        tile[rr][tx] = x[(long long)srow * N_CELL + (c0 + tx)] * wv;
    }

    __syncthreads();

    // Store phase: transposed. 32 consecutive r per warp -> 128B coalesced.
    #pragma unroll
    for (int j = 0; j < 4; j++) {
        const int cc = ty + j * 8;           // column within tile
        out[(long long)(c0 + cc) * R_TOTAL + (r0 + tx)] = tile[tx][cc];
    }
}

extern "C" void kernel_launch(void* const* d_in, const int* in_sizes, int n_in,
                              void* d_out, int out_size)
{
    // Bind inputs by element count (robust to metadata ordering):
    //   x = 10,240,000 ; weight = 50 ; idx = 100,000
    const float* x   = nullptr;
    const float* w   = nullptr;
    const int*   idx = nullptr;
    for (int i = 0; i < n_in; i++) {
        if (in_sizes[i] == N_FEATURE * N_CELL)      x   = (const float*)d_in[i];
        else if (in_sizes[i] == N_CT)               w   = (const float*)d_in[i];
        else if (in_sizes[i] == R_TOTAL)            idx = (const int*)d_in[i];
    }
    float* out = (float*)d_out;

    dim3 grid(R_TOTAL / 32, N_CELL / 32);    // (3125, 16)
    dim3 block(32, 8);
    celltype_scale_transpose_kernel<<<grid, block>>>(x, w, idx, out);
}